// round 3
// baseline (speedup 1.0000x reference)
#include <cuda_runtime.h>
#include <cuda_bf16.h>
#include <math.h>

#define N_NODES 65536
#define NN      131072          // both trees
#define MDIM    256
#define TM3     768
#define VOCABSZ 1000
#define MAXLEV  64

// ---------------- device scratch (static, allowed) ----------------
__device__ float g_hsum[(size_t)NN * MDIM];
__device__ float g_fcsum[(size_t)NN * MDIM];
__device__ float g_c[(size_t)NN * MDIM];
__device__ float g_h[(size_t)NN * MDIM];
__device__ float g_EA[(size_t)VOCABSZ * TM3];
__device__ float g_EB[(size_t)VOCABSZ * MDIM];
__device__ float g_rootc[2 * MDIM];

__device__ int g_parent[NN];
__device__ int g_tok[NN];
__device__ int g_anc[2][NN];
__device__ int g_dist[2][NN];
__device__ int g_childcnt[NN];
__device__ int g_lvlcnt_int[MAXLEV];
__device__ int g_lvlcnt_leaf[MAXLEV];
__device__ int g_lvloff[MAXLEV];
__device__ int g_curs_int[MAXLEV];
__device__ int g_curs_leaf[MAXLEV];
__device__ int g_order[NN];

__device__ __forceinline__ float sigm(float x) { return 1.f / (1.f + __expf(-x)); }

// ---------------- setup ----------------
__global__ void clear_kernel() {
    size_t i = (size_t)blockIdx.x * blockDim.x + threadIdx.x;
    size_t tot4 = (size_t)NN * MDIM / 4;   // 8388608 float4s
    if (i < tot4) {
        float4 z = make_float4(0.f, 0.f, 0.f, 0.f);
        reinterpret_cast<float4*>(g_hsum)[i] = z;
        reinterpret_cast<float4*>(g_fcsum)[i] = z;
    }
    if (i < NN) g_childcnt[i] = 0;
    if (i < MAXLEV) {
        g_lvlcnt_int[i] = 0; g_lvlcnt_leaf[i] = 0;
        g_curs_int[i] = 0;   g_curs_leaf[i] = 0;
    }
}

__global__ void setup_kernel(const int* __restrict__ lt, const int* __restrict__ lp,
                             const int* __restrict__ rt, const int* __restrict__ rp) {
    int g = blockIdx.x * blockDim.x + threadIdx.x;
    if (g >= NN) return;
    int tok, par; bool root;
    if (g < N_NODES) {
        tok = lt[g]; root = (g == 0);
        par = root ? g : lp[g];
    } else {
        int i = g - N_NODES;
        tok = rt[i]; root = (i == 0);
        par = root ? g : (N_NODES + rp[i]);
    }
    g_tok[g] = tok; g_parent[g] = par;
    g_anc[0][g] = par;                  // root: self-loop
    g_dist[0][g] = root ? 0 : 1;
    if (!root) atomicAdd(&g_childcnt[par], 1);
}

__global__ void doubling_kernel(int src) {
    int g = blockIdx.x * blockDim.x + threadIdx.x;
    if (g >= NN) return;
    int a = g_anc[src][g];
    g_dist[1 - src][g] = g_dist[src][g] + g_dist[src][a];
    g_anc[1 - src][g]  = g_anc[src][a];
}

__global__ void hist_kernel() {
    int g = blockIdx.x * blockDim.x + threadIdx.x;
    if (g >= NN) return;
    int d = g_dist[0][g]; if (d > MAXLEV - 1) d = MAXLEV - 1;
    if (g_childcnt[g] > 0) atomicAdd(&g_lvlcnt_int[d], 1);
    else                   atomicAdd(&g_lvlcnt_leaf[d], 1);
}

__global__ void scan_kernel() {
    if (threadIdx.x == 0) {
        int off = 0;
        for (int l = 0; l < MAXLEV; l++) {
            g_lvloff[l] = off;
            off += g_lvlcnt_int[l] + g_lvlcnt_leaf[l];
        }
    }
}

__global__ void scatter_kernel() {
    int g = blockIdx.x * blockDim.x + threadIdx.x;
    if (g >= NN) return;
    int d = g_dist[0][g]; if (d > MAXLEV - 1) d = MAXLEV - 1;
    int base = g_lvloff[d];
    if (g_childcnt[g] > 0) {
        int p = atomicAdd(&g_curs_int[d], 1);
        g_order[base + p] = g;
    } else {
        int p = atomicAdd(&g_curs_leaf[d], 1);
        g_order[base + g_lvlcnt_int[d] + p] = g;
    }
}

// EA[v][j] = sum_k emb[v][k]*Wioux[k][j] + bioux[j] + biouh[j]   (j<768)
// EB[v][j] = sum_k emb[v][k]*Wfx[k][j]  + bfx[j]  + bfh[j]       (j<256)
__global__ void eaeb_kernel(const float* __restrict__ emb,
                            const float* __restrict__ Wioux, const float* __restrict__ bioux,
                            const float* __restrict__ biouh,
                            const float* __restrict__ Wfx, const float* __restrict__ bfx,
                            const float* __restrict__ bfh) {
    int v = blockIdx.x;       // 0..999
    int chunk = blockIdx.y;   // 0..3
    __shared__ float xs[MDIM];
    int t = threadIdx.x;
    xs[t] = emb[(size_t)v * MDIM + t];
    __syncthreads();
    if (chunk < 3) {
        int j = chunk * 256 + t;
        float acc = bioux[j] + biouh[j];
        #pragma unroll 8
        for (int k = 0; k < MDIM; k++) acc += xs[k] * Wioux[(size_t)k * TM3 + j];
        g_EA[(size_t)v * TM3 + j] = acc;
    } else {
        int j = t;
        float acc = bfx[j] + bfh[j];
        #pragma unroll 8
        for (int k = 0; k < MDIM; k++) acc += xs[k] * Wfx[(size_t)k * MDIM + j];
        g_EB[(size_t)v * MDIM + j] = acc;
    }
}

// ---------------- level kernel 1: iou GEMM + cell update ----------------
// Internal nodes: iou = h_sum @ Wiouh (+EA[token]); thread t owns cols t, t+256, t+512.
// Leaf nodes: iou = EA[token] only.
__global__ void __launch_bounds__(256) level1_kernel(int lev, const float* __restrict__ Wiouh) {
    const int cntI = g_lvlcnt_int[lev];
    const int cntL = g_lvlcnt_leaf[lev];
    const int base = g_lvloff[lev];
    const int tilesI = (cntI + 15) >> 4;
    const int tilesL = (cntL + 15) >> 4;
    const int total = tilesI + tilesL;
    __shared__ float Bs[8][TM3];
    __shared__ float As[16][8];
    __shared__ int gid_s[16];
    const int t = threadIdx.x;

    for (int tile = blockIdx.x; tile < total; tile += gridDim.x) {
        if (tile < tilesI) {
            int r0 = tile * 16;
            int nr = min(16, cntI - r0);
            if (t < 16) gid_s[t] = (t < nr) ? g_order[base + r0 + t] : 0;
            __syncthreads();
            float accI[16], accO[16], accU[16];
            #pragma unroll
            for (int r = 0; r < 16; r++) { accI[r] = 0.f; accO[r] = 0.f; accU[r] = 0.f; }

            for (int k0 = 0; k0 < MDIM; k0 += 8) {
                if (t < 128) {
                    int r = t >> 3, k = t & 7;
                    As[r][k] = (r < nr) ? g_hsum[(size_t)gid_s[r] * MDIM + k0 + k] : 0.f;
                }
                #pragma unroll
                for (int i = 0; i < 24; i++) {
                    int idx = t + i * 256;
                    int k = idx / TM3, j = idx - k * TM3;
                    Bs[k][j] = Wiouh[(size_t)(k0 + k) * TM3 + j];
                }
                __syncthreads();
                #pragma unroll
                for (int k = 0; k < 8; k++) {
                    float b0 = Bs[k][t], b1 = Bs[k][256 + t], b2 = Bs[k][512 + t];
                    #pragma unroll
                    for (int r = 0; r < 16; r++) {
                        float a = As[r][k];
                        accI[r] += a * b0; accO[r] += a * b1; accU[r] += a * b2;
                    }
                }
                __syncthreads();
            }
            for (int r = 0; r < nr; r++) {
                int g = gid_s[r];
                int tok = g_tok[g];
                const float* ea = &g_EA[(size_t)tok * TM3];
                float ig = accI[r] + ea[t];
                float og = accO[r] + ea[256 + t];
                float ug = accU[r] + ea[512 + t];
                float cc = sigm(ig) * tanhf(ug) + g_fcsum[(size_t)g * MDIM + t];
                float hh = sigm(og) * tanhf(cc);
                g_c[(size_t)g * MDIM + t] = cc;
                g_h[(size_t)g * MDIM + t] = hh;
                if (g == 0)            g_rootc[t] = cc;
                else if (g == N_NODES) g_rootc[256 + t] = cc;
            }
            __syncthreads();
        } else {
            int lt2 = tile - tilesI;
            int r0 = lt2 * 16;
            int nr = min(16, cntL - r0);
            int lbase = base + cntI + r0;
            if (t < 16) gid_s[t] = (t < nr) ? g_order[lbase + t] : 0;
            __syncthreads();
            for (int r = 0; r < nr; r++) {
                int g = gid_s[r];
                int tok = g_tok[g];
                const float* ea = &g_EA[(size_t)tok * TM3];
                float cc = sigm(ea[t]) * tanhf(ea[512 + t]);
                float hh = sigm(ea[256 + t]) * tanhf(cc);
                g_c[(size_t)g * MDIM + t] = cc;
                g_h[(size_t)g * MDIM + t] = hh;
            }
            __syncthreads();
        }
    }
}

// ---------------- level kernel 2: f GEMM + parent scatter ----------------
// acc = h @ Wfh ; f = sigm(acc + EB[tok(parent)]) ; h_sum[p]+=h ; fc_sum[p]+=f*c
__global__ void __launch_bounds__(256) level2_kernel(int lev, const float* __restrict__ Wfh) {
    const int cnt = g_lvlcnt_int[lev] + g_lvlcnt_leaf[lev];
    const int base = g_lvloff[lev];
    const int rowTiles = (cnt + 63) >> 6;
    const int total = rowTiles * 4;
    __shared__ __align__(16) float As[16][68];
    __shared__ __align__(16) float Bs[16][64];
    __shared__ int gid_s[64];
    const int t = threadIdx.x;
    const int tx = t & 15, ty = t >> 4;

    for (int tile = blockIdx.x; tile < total; tile += gridDim.x) {
        int rt = tile >> 2, ct = tile & 3;
        int r0 = rt * 64, c0 = ct * 64;
        int nr = min(64, cnt - r0);
        if (t < 64) gid_s[t] = (t < nr) ? g_order[base + r0 + t] : 0;
        __syncthreads();
        float acc[4][4];
        #pragma unroll
        for (int i = 0; i < 4; i++)
            #pragma unroll
            for (int j = 0; j < 4; j++) acc[i][j] = 0.f;

        for (int k0 = 0; k0 < MDIM; k0 += 16) {
            #pragma unroll
            for (int i = 0; i < 4; i++) {
                int idx = t + i * 256;
                int r = idx >> 4, k = idx & 15;
                As[k][r] = (r < nr) ? g_h[(size_t)gid_s[r] * MDIM + k0 + k] : 0.f;
            }
            #pragma unroll
            for (int i = 0; i < 4; i++) {
                int idx = t + i * 256;
                int k = idx >> 6, c = idx & 63;
                Bs[k][c] = Wfh[(size_t)(k0 + k) * MDIM + c0 + c];
            }
            __syncthreads();
            #pragma unroll
            for (int k = 0; k < 16; k++) {
                float4 a4 = *(const float4*)&As[k][ty * 4];
                float4 b4 = *(const float4*)&Bs[k][tx * 4];
                acc[0][0] += a4.x * b4.x; acc[0][1] += a4.x * b4.y; acc[0][2] += a4.x * b4.z; acc[0][3] += a4.x * b4.w;
                acc[1][0] += a4.y * b4.x; acc[1][1] += a4.y * b4.y; acc[1][2] += a4.y * b4.z; acc[1][3] += a4.y * b4.w;
                acc[2][0] += a4.z * b4.x; acc[2][1] += a4.z * b4.y; acc[2][2] += a4.z * b4.z; acc[2][3] += a4.z * b4.w;
                acc[3][0] += a4.w * b4.x; acc[3][1] += a4.w * b4.y; acc[3][2] += a4.w * b4.z; acc[3][3] += a4.w * b4.w;
            }
            __syncthreads();
        }
        #pragma unroll
        for (int i = 0; i < 4; i++) {
            int r = ty * 4 + i;
            if (r < nr) {
                int g = gid_s[r];
                if (g != 0 && g != N_NODES) {
                    int p = g_parent[g];
                    int ptok = g_tok[p];
                    #pragma unroll
                    for (int j = 0; j < 4; j++) {
                        int cidx = c0 + tx * 4 + j;
                        float f = sigm(acc[i][j] + g_EB[(size_t)ptok * MDIM + cidx]);
                        float hv = g_h[(size_t)g * MDIM + cidx];
                        float cv = g_c[(size_t)g * MDIM + cidx];
                        atomicAdd(&g_hsum[(size_t)p * MDIM + cidx], hv);
                        atomicAdd(&g_fcsum[(size_t)p * MDIM + cidx], f * cv);
                    }
                }
            }
        }
        __syncthreads();
    }
}

// ---------------- similarity head ----------------
__global__ void head_kernel(const float* __restrict__ Wh, const float* __restrict__ bh,
                            const float* __restrict__ Wp, const float* __restrict__ bp,
                            float* __restrict__ out) {
    __shared__ float vec[512];
    __shared__ float hid[256];
    __shared__ float r0s[8], r1s[8];
    int t = threadIdx.x;
    float cl = g_rootc[t], cr = g_rootc[256 + t];
    vec[t] = cl * cr;
    vec[256 + t] = fabsf(cl - cr);
    __syncthreads();
    float acc = bh[t];
    #pragma unroll 8
    for (int k = 0; k < 512; k++) acc += vec[k] * Wh[(size_t)k * 256 + t];
    hid[t] = 1.f / (1.f + expf(-acc));
    __syncthreads();
    float p0 = hid[t] * Wp[t * 2 + 0];
    float p1 = hid[t] * Wp[t * 2 + 1];
    #pragma unroll
    for (int o = 16; o > 0; o >>= 1) {
        p0 += __shfl_down_sync(0xffffffffu, p0, o);
        p1 += __shfl_down_sync(0xffffffffu, p1, o);
    }
    if ((t & 31) == 0) { r0s[t >> 5] = p0; r1s[t >> 5] = p1; }
    __syncthreads();
    if (t == 0) {
        float l0 = bp[0], l1 = bp[1];
        #pragma unroll
        for (int w = 0; w < 8; w++) { l0 += r0s[w]; l1 += r1s[w]; }
        float m = fmaxf(l0, l1);
        float e0 = expf(l0 - m), e1 = expf(l1 - m);
        float inv = 1.f / (e0 + e1);
        out[0] = e0 * inv;
        out[1] = e1 * inv;
    }
}

// ---------------- host launch ----------------
extern "C" void kernel_launch(void* const* d_in, const int* in_sizes, int n_in,
                              void* d_out, int out_size) {
    const int*   l_tokens = (const int*)  d_in[0];
    const int*   l_parent = (const int*)  d_in[1];
    const int*   r_tokens = (const int*)  d_in[2];
    const int*   r_parent = (const int*)  d_in[3];
    const float* emb_W    = (const float*)d_in[4];
    const float* Wioux    = (const float*)d_in[5];
    const float* bioux    = (const float*)d_in[6];
    const float* Wiouh    = (const float*)d_in[7];
    const float* biouh    = (const float*)d_in[8];
    const float* Wfx      = (const float*)d_in[9];
    const float* bfx      = (const float*)d_in[10];
    const float* Wfh      = (const float*)d_in[11];
    const float* bfh      = (const float*)d_in[12];
    const float* Wh       = (const float*)d_in[13];
    const float* bh       = (const float*)d_in[14];
    const float* Wp       = (const float*)d_in[15];
    const float* bp       = (const float*)d_in[16];
    float* out = (float*)d_out;

    clear_kernel<<<32768, 256>>>();
    setup_kernel<<<NN / 256, 256>>>(l_tokens, l_parent, r_tokens, r_parent);
    for (int it = 0; it < 8; it++)
        doubling_kernel<<<NN / 256, 256>>>(it & 1);
    hist_kernel<<<NN / 256, 256>>>();
    scan_kernel<<<1, 32>>>();
    scatter_kernel<<<NN / 256, 256>>>();
    eaeb_kernel<<<dim3(VOCABSZ, 4), 256>>>(emb_W, Wioux, bioux, biouh, Wfx, bfx, bfh);

    for (int lev = MAXLEV - 1; lev >= 0; lev--) {
        level1_kernel<<<512, 256>>>(lev, Wiouh);
        level2_kernel<<<512, 256>>>(lev, Wfh);
    }
    head_kernel<<<1, 256>>>(Wh, bh, Wp, bp, out);
}

// round 4
// speedup vs baseline: 1.1289x; 1.1289x over previous
#include <cuda_runtime.h>
#include <cuda_bf16.h>
#include <math.h>

#define N_NODES 65536
#define NN      131072          // both trees
#define MDIM    256
#define TM3     768
#define VOCABSZ 1000
#define MAXLEV  64
#define NB      296             // persistent grid: 2 CTAs/SM on 148 SMs

// ---------------- device scratch (static, allowed) ----------------
__device__ float g_hsum[(size_t)NN * MDIM];
__device__ float g_fcsum[(size_t)NN * MDIM];
__device__ float g_c[(size_t)NN * MDIM];
__device__ float g_h[(size_t)NN * MDIM];
__device__ float g_EA[(size_t)VOCABSZ * TM3];
__device__ float g_EB[(size_t)VOCABSZ * MDIM];
__device__ float g_rootc[2 * MDIM];

__device__ int g_parent[NN];
__device__ int g_tok[NN];
__device__ int g_anc[2][NN];
__device__ int g_dist[2][NN];
__device__ int g_childcnt[NN];
__device__ int g_lvlcnt_int[MAXLEV];
__device__ int g_lvlcnt_leaf[MAXLEV];
__device__ int g_lvloff[MAXLEV];
__device__ int g_curs_int[MAXLEV];
__device__ int g_curs_leaf[MAXLEV];
__device__ int g_order[NN];
__device__ int g_maxlev;

// grid barrier state (self-resetting; no per-launch init needed)
__device__ unsigned g_bcount = 0;
__device__ volatile unsigned g_bgen = 0;

__device__ __forceinline__ float sigm(float x) { return 1.f / (1.f + __expf(-x)); }

__device__ __forceinline__ void gsync() {
    __syncthreads();
    if (threadIdx.x == 0) {
        __threadfence();
        unsigned my = g_bgen;
        if (atomicInc(&g_bcount, gridDim.x - 1) == gridDim.x - 1) {
            g_bgen = my + 1;
        } else {
            while (g_bgen == my) { }
        }
        __threadfence();
    }
    __syncthreads();
}

// ---------------- setup ----------------
__global__ void clear_kernel() {
    size_t i = (size_t)blockIdx.x * blockDim.x + threadIdx.x;
    size_t tot4 = (size_t)NN * MDIM / 4;
    if (i < tot4) {
        float4 z = make_float4(0.f, 0.f, 0.f, 0.f);
        reinterpret_cast<float4*>(g_hsum)[i] = z;
        reinterpret_cast<float4*>(g_fcsum)[i] = z;
    }
    if (i < NN) g_childcnt[i] = 0;
    if (i < MAXLEV) {
        g_lvlcnt_int[i] = 0; g_lvlcnt_leaf[i] = 0;
        g_curs_int[i] = 0;   g_curs_leaf[i] = 0;
    }
}

__global__ void setup_kernel(const int* __restrict__ lt, const int* __restrict__ lp,
                             const int* __restrict__ rt, const int* __restrict__ rp) {
    int g = blockIdx.x * blockDim.x + threadIdx.x;
    if (g >= NN) return;
    int tok, par; bool root;
    if (g < N_NODES) {
        tok = lt[g]; root = (g == 0);
        par = root ? g : lp[g];
    } else {
        int i = g - N_NODES;
        tok = rt[i]; root = (i == 0);
        par = root ? g : (N_NODES + rp[i]);
    }
    g_tok[g] = tok; g_parent[g] = par;
    g_anc[0][g] = par;                  // root: self-loop
    g_dist[0][g] = root ? 0 : 1;
    if (!root) atomicAdd(&g_childcnt[par], 1);
}

__global__ void doubling_kernel(int src) {
    int g = blockIdx.x * blockDim.x + threadIdx.x;
    if (g >= NN) return;
    int a = g_anc[src][g];
    g_dist[1 - src][g] = g_dist[src][g] + g_dist[src][a];
    g_anc[1 - src][g]  = g_anc[src][a];
}

__global__ void hist_kernel() {
    int g = blockIdx.x * blockDim.x + threadIdx.x;
    if (g >= NN) return;
    int d = g_dist[0][g]; if (d > MAXLEV - 1) d = MAXLEV - 1;
    if (g_childcnt[g] > 0) atomicAdd(&g_lvlcnt_int[d], 1);
    else                   atomicAdd(&g_lvlcnt_leaf[d], 1);
}

__global__ void scan_kernel() {
    if (threadIdx.x == 0) {
        int off = 0, maxl = 0;
        for (int l = 0; l < MAXLEV; l++) {
            g_lvloff[l] = off;
            int c = g_lvlcnt_int[l] + g_lvlcnt_leaf[l];
            if (c > 0) maxl = l;
            off += c;
        }
        g_maxlev = maxl;
    }
}

__global__ void scatter_kernel() {
    int g = blockIdx.x * blockDim.x + threadIdx.x;
    if (g >= NN) return;
    int d = g_dist[0][g]; if (d > MAXLEV - 1) d = MAXLEV - 1;
    int base = g_lvloff[d];
    if (g_childcnt[g] > 0) {
        int p = atomicAdd(&g_curs_int[d], 1);
        g_order[base + p] = g;
    } else {
        int p = atomicAdd(&g_curs_leaf[d], 1);
        g_order[base + g_lvlcnt_int[d] + p] = g;
    }
}

// EA[v][j] = emb[v]@Wioux[:,j] + bioux[j] + biouh[j]   (j<768)
// EB[v][j] = emb[v]@Wfx[:,j]  + bfx[j]  + bfh[j]       (j<256)
__global__ void eaeb_kernel(const float* __restrict__ emb,
                            const float* __restrict__ Wioux, const float* __restrict__ bioux,
                            const float* __restrict__ biouh,
                            const float* __restrict__ Wfx, const float* __restrict__ bfx,
                            const float* __restrict__ bfh) {
    int v = blockIdx.x;       // 0..999
    int chunk = blockIdx.y;   // 0..3
    __shared__ float xs[MDIM];
    int t = threadIdx.x;
    xs[t] = emb[(size_t)v * MDIM + t];
    __syncthreads();
    if (chunk < 3) {
        int j = chunk * 256 + t;
        float acc = bioux[j] + biouh[j];
        #pragma unroll 8
        for (int k = 0; k < MDIM; k++) acc += xs[k] * Wioux[(size_t)k * TM3 + j];
        g_EA[(size_t)v * TM3 + j] = acc;
    } else {
        int j = t;
        float acc = bfx[j] + bfh[j];
        #pragma unroll 8
        for (int k = 0; k < MDIM; k++) acc += xs[k] * Wfx[(size_t)k * MDIM + j];
        g_EB[(size_t)v * MDIM + j] = acc;
    }
}

// ---------------- persistent level-loop kernel ----------------
union SmemU {
    struct { float Bs[8][TM3]; float As[16][8]; int gid[16]; } p1;
    struct { float As[16][68]; float Bs[16][64]; int gid[64]; } p2;
    struct { float vec[512]; float hid[256]; float r0s[8], r1s[8]; } hd;
};

__global__ void __launch_bounds__(256, 2)
persist_kernel(const float* __restrict__ Wiouh, const float* __restrict__ Wfh,
               const float* __restrict__ Wh, const float* __restrict__ bh,
               const float* __restrict__ Wp, const float* __restrict__ bp,
               float* __restrict__ out) {
    __shared__ SmemU sm;
    const int t = threadIdx.x;
    const int maxlev = g_maxlev;

    for (int lev = maxlev; lev >= 0; lev--) {
        // ===== phase 1: iou GEMM (internal) / gather (leaf) + cell update =====
        {
            const int cntI = g_lvlcnt_int[lev];
            const int cntL = g_lvlcnt_leaf[lev];
            const int base = g_lvloff[lev];
            const int tilesI = (cntI + 15) >> 4;
            const int tilesL = (cntL + 15) >> 4;
            const int total = tilesI + tilesL;

            for (int tile = blockIdx.x; tile < total; tile += gridDim.x) {
                if (tile < tilesI) {
                    int r0 = tile * 16;
                    int nr = min(16, cntI - r0);
                    if (t < 16) sm.p1.gid[t] = (t < nr) ? g_order[base + r0 + t] : 0;
                    __syncthreads();
                    float accI[16], accO[16], accU[16];
                    #pragma unroll
                    for (int r = 0; r < 16; r++) { accI[r] = 0.f; accO[r] = 0.f; accU[r] = 0.f; }

                    for (int k0 = 0; k0 < MDIM; k0 += 8) {
                        if (t < 128) {
                            int r = t >> 3, k = t & 7;
                            sm.p1.As[r][k] = (r < nr) ? g_hsum[(size_t)sm.p1.gid[r] * MDIM + k0 + k] : 0.f;
                        }
                        #pragma unroll
                        for (int i = 0; i < 24; i++) {
                            int idx = t + i * 256;
                            int k = idx / TM3, j = idx - k * TM3;
                            sm.p1.Bs[k][j] = Wiouh[(size_t)(k0 + k) * TM3 + j];
                        }
                        __syncthreads();
                        #pragma unroll
                        for (int k = 0; k < 8; k++) {
                            float b0 = sm.p1.Bs[k][t], b1 = sm.p1.Bs[k][256 + t], b2 = sm.p1.Bs[k][512 + t];
                            #pragma unroll
                            for (int r = 0; r < 16; r++) {
                                float a = sm.p1.As[r][k];
                                accI[r] += a * b0; accO[r] += a * b1; accU[r] += a * b2;
                            }
                        }
                        __syncthreads();
                    }
                    // epilogue: fully unrolled, static register indexing (no local spills)
                    #pragma unroll
                    for (int r = 0; r < 16; r++) {
                        if (r < nr) {
                            int g = sm.p1.gid[r];
                            int tok = g_tok[g];
                            const float* ea = &g_EA[(size_t)tok * TM3];
                            float ig = accI[r] + ea[t];
                            float og = accO[r] + ea[256 + t];
                            float ug = accU[r] + ea[512 + t];
                            float cc = sigm(ig) * tanhf(ug) + g_fcsum[(size_t)g * MDIM + t];
                            float hh = sigm(og) * tanhf(cc);
                            g_c[(size_t)g * MDIM + t] = cc;
                            g_h[(size_t)g * MDIM + t] = hh;
                            if (g == 0)            g_rootc[t] = cc;
                            else if (g == N_NODES) g_rootc[256 + t] = cc;
                        }
                    }
                    __syncthreads();
                } else {
                    int lt2 = tile - tilesI;
                    int r0 = lt2 * 16;
                    int nr = min(16, cntL - r0);
                    int lbase = base + cntI + r0;
                    if (t < 16) sm.p1.gid[t] = (t < nr) ? g_order[lbase + t] : 0;
                    __syncthreads();
                    for (int r = 0; r < nr; r++) {
                        int g = sm.p1.gid[r];
                        int tok = g_tok[g];
                        const float* ea = &g_EA[(size_t)tok * TM3];
                        float cc = sigm(ea[t]) * tanhf(ea[512 + t]);
                        float hh = sigm(ea[256 + t]) * tanhf(cc);
                        g_c[(size_t)g * MDIM + t] = cc;
                        g_h[(size_t)g * MDIM + t] = hh;
                    }
                    __syncthreads();
                }
            }
        }
        gsync();

        // ===== phase 2: f GEMM (h @ Wfh) + scatter into parents =====
        if (lev > 0) {
            const int cnt = g_lvlcnt_int[lev] + g_lvlcnt_leaf[lev];
            const int base = g_lvloff[lev];
            const int rowTiles = (cnt + 63) >> 6;
            const int total = rowTiles * 4;
            const int tx = t & 15, ty = t >> 4;

            for (int tile = blockIdx.x; tile < total; tile += gridDim.x) {
                int rt2 = tile >> 2, ct = tile & 3;
                int r0 = rt2 * 64, c0 = ct * 64;
                int nr = min(64, cnt - r0);
                if (t < 64) sm.p2.gid[t] = (t < nr) ? g_order[base + r0 + t] : 0;
                __syncthreads();
                float acc[4][4];
                #pragma unroll
                for (int i = 0; i < 4; i++)
                    #pragma unroll
                    for (int j = 0; j < 4; j++) acc[i][j] = 0.f;

                for (int k0 = 0; k0 < MDIM; k0 += 16) {
                    #pragma unroll
                    for (int i = 0; i < 4; i++) {
                        int idx = t + i * 256;
                        int r = idx >> 4, k = idx & 15;
                        sm.p2.As[k][r] = (r < nr) ? g_h[(size_t)sm.p2.gid[r] * MDIM + k0 + k] : 0.f;
                    }
                    #pragma unroll
                    for (int i = 0; i < 4; i++) {
                        int idx = t + i * 256;
                        int k = idx >> 6, c = idx & 63;
                        sm.p2.Bs[k][c] = Wfh[(size_t)(k0 + k) * MDIM + c0 + c];
                    }
                    __syncthreads();
                    #pragma unroll
                    for (int k = 0; k < 16; k++) {
                        float4 a4 = *(const float4*)&sm.p2.As[k][ty * 4];
                        float4 b4 = *(const float4*)&sm.p2.Bs[k][tx * 4];
                        acc[0][0] += a4.x * b4.x; acc[0][1] += a4.x * b4.y; acc[0][2] += a4.x * b4.z; acc[0][3] += a4.x * b4.w;
                        acc[1][0] += a4.y * b4.x; acc[1][1] += a4.y * b4.y; acc[1][2] += a4.y * b4.z; acc[1][3] += a4.y * b4.w;
                        acc[2][0] += a4.z * b4.x; acc[2][1] += a4.z * b4.y; acc[2][2] += a4.z * b4.z; acc[2][3] += a4.z * b4.w;
                        acc[3][0] += a4.w * b4.x; acc[3][1] += a4.w * b4.y; acc[3][2] += a4.w * b4.z; acc[3][3] += a4.w * b4.w;
                    }
                    __syncthreads();
                }
                #pragma unroll
                for (int i = 0; i < 4; i++) {
                    int r = ty * 4 + i;
                    if (r < nr) {
                        int g = sm.p2.gid[r];
                        if (g != 0 && g != N_NODES) {
                            int p = g_parent[g];
                            int ptok = g_tok[p];
                            #pragma unroll
                            for (int j = 0; j < 4; j++) {
                                int cidx = c0 + tx * 4 + j;
                                float f = sigm(acc[i][j] + g_EB[(size_t)ptok * MDIM + cidx]);
                                float hv = g_h[(size_t)g * MDIM + cidx];
                                float cv = g_c[(size_t)g * MDIM + cidx];
                                atomicAdd(&g_hsum[(size_t)p * MDIM + cidx], hv);
                                atomicAdd(&g_fcsum[(size_t)p * MDIM + cidx], f * cv);
                            }
                        }
                    }
                }
                __syncthreads();
            }
            gsync();
        }
    }

    // ===== similarity head (block 0 only, after final gsync in loop) =====
    if (blockIdx.x == 0) {
        float cl = g_rootc[t], cr = g_rootc[256 + t];
        sm.hd.vec[t] = cl * cr;
        sm.hd.vec[256 + t] = fabsf(cl - cr);
        __syncthreads();
        float acc = bh[t];
        #pragma unroll 8
        for (int k = 0; k < 512; k++) acc += sm.hd.vec[k] * Wh[(size_t)k * 256 + t];
        sm.hd.hid[t] = 1.f / (1.f + expf(-acc));
        __syncthreads();
        float p0 = sm.hd.hid[t] * Wp[t * 2 + 0];
        float p1 = sm.hd.hid[t] * Wp[t * 2 + 1];
        #pragma unroll
        for (int o = 16; o > 0; o >>= 1) {
            p0 += __shfl_down_sync(0xffffffffu, p0, o);
            p1 += __shfl_down_sync(0xffffffffu, p1, o);
        }
        if ((t & 31) == 0) { sm.hd.r0s[t >> 5] = p0; sm.hd.r1s[t >> 5] = p1; }
        __syncthreads();
        if (t == 0) {
            float l0 = bp[0], l1 = bp[1];
            #pragma unroll
            for (int w = 0; w < 8; w++) { l0 += sm.hd.r0s[w]; l1 += sm.hd.r1s[w]; }
            float m = fmaxf(l0, l1);
            float e0 = expf(l0 - m), e1 = expf(l1 - m);
            float inv = 1.f / (e0 + e1);
            out[0] = e0 * inv;
            out[1] = e1 * inv;
        }
    }
}

// ---------------- host launch ----------------
extern "C" void kernel_launch(void* const* d_in, const int* in_sizes, int n_in,
                              void* d_out, int out_size) {
    const int*   l_tokens = (const int*)  d_in[0];
    const int*   l_parent = (const int*)  d_in[1];
    const int*   r_tokens = (const int*)  d_in[2];
    const int*   r_parent = (const int*)  d_in[3];
    const float* emb_W    = (const float*)d_in[4];
    const float* Wioux    = (const float*)d_in[5];
    const float* bioux    = (const float*)d_in[6];
    const float* Wiouh    = (const float*)d_in[7];
    const float* biouh    = (const float*)d_in[8];
    const float* Wfx      = (const float*)d_in[9];
    const float* bfx      = (const float*)d_in[10];
    const float* Wfh      = (const float*)d_in[11];
    const float* bfh      = (const float*)d_in[12];
    const float* Wh       = (const float*)d_in[13];
    const float* bh       = (const float*)d_in[14];
    const float* Wp       = (const float*)d_in[15];
    const float* bp       = (const float*)d_in[16];
    float* out = (float*)d_out;

    clear_kernel<<<32768, 256>>>();
    setup_kernel<<<NN / 256, 256>>>(l_tokens, l_parent, r_tokens, r_parent);
    for (int it = 0; it < 8; it++)
        doubling_kernel<<<NN / 256, 256>>>(it & 1);
    hist_kernel<<<NN / 256, 256>>>();
    scan_kernel<<<1, 32>>>();
    scatter_kernel<<<NN / 256, 256>>>();
    eaeb_kernel<<<dim3(VOCABSZ, 4), 256>>>(emb_W, Wioux, bioux, biouh, Wfx, bfx, bfh);

    persist_kernel<<<NB, 256>>>(Wiouh, Wfh, Wh, bh, Wp, bp, out);
}

// round 5
// speedup vs baseline: 2.0108x; 1.7811x over previous
#include <cuda_runtime.h>
#include <cuda_bf16.h>
#include <math.h>

#define N_NODES 65536
#define NN      131072          // both trees
#define MDIM    256
#define TM3     768
#define VOCABSZ 1000
#define MAXLEV  64
#define NB      296             // persistent grid: 2 CTAs/SM on 148 SMs

// ---------------- device scratch (static, allowed) ----------------
__device__ float g_hsum[(size_t)NN * MDIM];
__device__ float g_fcsum[(size_t)NN * MDIM];
__device__ float g_EA[(size_t)VOCABSZ * TM3];
__device__ float g_EB[(size_t)VOCABSZ * MDIM];
__device__ float g_HL[(size_t)VOCABSZ * MDIM];   // leaf h by token
__device__ float g_CL[(size_t)VOCABSZ * MDIM];   // leaf c by token
__device__ float g_FH[(size_t)VOCABSZ * MDIM];   // leaf h @ Wfh by token
__device__ float g_rootc[2 * MDIM];

__device__ int g_parent[NN];
__device__ int g_tok[NN];
__device__ int g_anc[2][NN];
__device__ int g_dist[2][NN];
__device__ int g_childcnt[NN];
__device__ int g_lvlcnt_int[MAXLEV];
__device__ int g_lvlcnt_leaf[MAXLEV];
__device__ int g_lvloff[MAXLEV];
__device__ int g_curs_int[MAXLEV];
__device__ int g_curs_leaf[MAXLEV];
__device__ int g_order[NN];
__device__ int g_maxlev;

// grid barrier state (self-resetting)
__device__ unsigned g_bcount = 0;
__device__ volatile unsigned g_bgen = 0;

__device__ __forceinline__ float sigm(float x) { return 1.f / (1.f + __expf(-x)); }

__device__ __forceinline__ void gsync() {
    __syncthreads();
    if (threadIdx.x == 0) {
        __threadfence();
        unsigned my = g_bgen;
        if (atomicInc(&g_bcount, gridDim.x - 1) == gridDim.x - 1) {
            g_bgen = my + 1;
        } else {
            while (g_bgen == my) { }
        }
        __threadfence();
    }
    __syncthreads();
}

// ---------------- setup ----------------
__global__ void clear_kernel() {
    size_t i = (size_t)blockIdx.x * blockDim.x + threadIdx.x;
    size_t tot4 = (size_t)NN * MDIM / 4;
    if (i < tot4) {
        float4 z = make_float4(0.f, 0.f, 0.f, 0.f);
        reinterpret_cast<float4*>(g_hsum)[i] = z;
        reinterpret_cast<float4*>(g_fcsum)[i] = z;
    }
    if (i < NN) g_childcnt[i] = 0;
    if (i < MAXLEV) {
        g_lvlcnt_int[i] = 0; g_lvlcnt_leaf[i] = 0;
        g_curs_int[i] = 0;   g_curs_leaf[i] = 0;
    }
}

__global__ void setup_kernel(const int* __restrict__ lt, const int* __restrict__ lp,
                             const int* __restrict__ rt, const int* __restrict__ rp) {
    int g = blockIdx.x * blockDim.x + threadIdx.x;
    if (g >= NN) return;
    int tok, par; bool root;
    if (g < N_NODES) {
        tok = lt[g]; root = (g == 0);
        par = root ? g : lp[g];
    } else {
        int i = g - N_NODES;
        tok = rt[i]; root = (i == 0);
        par = root ? g : (N_NODES + rp[i]);
    }
    g_tok[g] = tok; g_parent[g] = par;
    g_anc[0][g] = par;                  // root: self-loop
    g_dist[0][g] = root ? 0 : 1;
    if (!root) atomicAdd(&g_childcnt[par], 1);
}

__global__ void doubling_kernel(int src) {
    int g = blockIdx.x * blockDim.x + threadIdx.x;
    if (g >= NN) return;
    int a = g_anc[src][g];
    g_dist[1 - src][g] = g_dist[src][g] + g_dist[src][a];
    g_anc[1 - src][g]  = g_anc[src][a];
}

__global__ void hist_kernel() {
    int g = blockIdx.x * blockDim.x + threadIdx.x;
    if (g >= NN) return;
    int d = g_dist[0][g]; if (d > MAXLEV - 1) d = MAXLEV - 1;
    if (g_childcnt[g] > 0) atomicAdd(&g_lvlcnt_int[d], 1);
    else                   atomicAdd(&g_lvlcnt_leaf[d], 1);
}

__global__ void scan_kernel() {
    if (threadIdx.x == 0) {
        int off = 0, maxl = 0;
        for (int l = 0; l < MAXLEV; l++) {
            g_lvloff[l] = off;
            int c = g_lvlcnt_int[l] + g_lvlcnt_leaf[l];
            if (c > 0) maxl = l;
            off += c;
        }
        g_maxlev = maxl;
    }
}

__global__ void scatter_kernel() {
    int g = blockIdx.x * blockDim.x + threadIdx.x;
    if (g >= NN) return;
    int d = g_dist[0][g]; if (d > MAXLEV - 1) d = MAXLEV - 1;
    int base = g_lvloff[d];
    if (g_childcnt[g] > 0) {
        int p = atomicAdd(&g_curs_int[d], 1);
        g_order[base + p] = g;
    } else {
        int p = atomicAdd(&g_curs_leaf[d], 1);
        g_order[base + g_lvlcnt_int[d] + p] = g;
    }
}

// EA[v][j] = emb[v]@Wioux[:,j] + bioux[j] + biouh[j]   (j<768)
// EB[v][j] = emb[v]@Wfx[:,j]  + bfx[j]  + bfh[j]       (j<256)
__global__ void eaeb_kernel(const float* __restrict__ emb,
                            const float* __restrict__ Wioux, const float* __restrict__ bioux,
                            const float* __restrict__ biouh,
                            const float* __restrict__ Wfx, const float* __restrict__ bfx,
                            const float* __restrict__ bfh) {
    int v = blockIdx.x;
    int chunk = blockIdx.y;
    __shared__ float xs[MDIM];
    int t = threadIdx.x;
    xs[t] = emb[(size_t)v * MDIM + t];
    __syncthreads();
    if (chunk < 3) {
        int j = chunk * 256 + t;
        float acc = bioux[j] + biouh[j];
        #pragma unroll 8
        for (int k = 0; k < MDIM; k++) acc += xs[k] * Wioux[(size_t)k * TM3 + j];
        g_EA[(size_t)v * TM3 + j] = acc;
    } else {
        int j = t;
        float acc = bfx[j] + bfh[j];
        #pragma unroll 8
        for (int k = 0; k < MDIM; k++) acc += xs[k] * Wfx[(size_t)k * MDIM + j];
        g_EB[(size_t)v * MDIM + j] = acc;
    }
}

// leaf h/c tables per vocab token: c = sig(EA_i)tanh(EA_u); h = sig(EA_o)tanh(c)
__global__ void leafhc_kernel() {
    int v = blockIdx.x, t = threadIdx.x;
    const float* ea = &g_EA[(size_t)v * TM3];
    float cc = sigm(ea[t]) * tanhf(ea[512 + t]);
    float hh = sigm(ea[256 + t]) * tanhf(cc);
    g_CL[(size_t)v * MDIM + t] = cc;
    g_HL[(size_t)v * MDIM + t] = hh;
}

// FH[v] = HL[v] @ Wfh
__global__ void leaffh_kernel(const float* __restrict__ Wfh) {
    int v = blockIdx.x, t = threadIdx.x;
    __shared__ float hs[MDIM];
    hs[t] = g_HL[(size_t)v * MDIM + t];
    __syncthreads();
    float acc = 0.f;
    #pragma unroll 8
    for (int k = 0; k < MDIM; k++) acc += hs[k] * Wfh[(size_t)k * MDIM + t];
    g_FH[(size_t)v * MDIM + t] = acc;
}

// bulk leaf scatter: all leaves contribute h and f*c to their parents upfront
__global__ void leafscatter_kernel() {
    int idx = blockIdx.x * blockDim.x + threadIdx.x;   // NN*64 threads
    int g = idx >> 6;
    int c = (idx & 63) * 4;
    if (g >= NN) return;
    if (g_childcnt[g] > 0) return;                     // internal
    int p = g_parent[g];
    int tok = g_tok[g], ptok = g_tok[p];
    float4 h4 = *(const float4*)&g_HL[(size_t)tok * MDIM + c];
    float4 c4 = *(const float4*)&g_CL[(size_t)tok * MDIM + c];
    float4 fh = *(const float4*)&g_FH[(size_t)tok * MDIM + c];
    float4 eb = *(const float4*)&g_EB[(size_t)ptok * MDIM + c];
    float f0 = sigm(fh.x + eb.x), f1 = sigm(fh.y + eb.y);
    float f2 = sigm(fh.z + eb.z), f3 = sigm(fh.w + eb.w);
    float* hs = &g_hsum[(size_t)p * MDIM + c];
    float* fs = &g_fcsum[(size_t)p * MDIM + c];
    atomicAdd(hs + 0, h4.x); atomicAdd(hs + 1, h4.y);
    atomicAdd(hs + 2, h4.z); atomicAdd(hs + 3, h4.w);
    atomicAdd(fs + 0, f0 * c4.x); atomicAdd(fs + 1, f1 * c4.y);
    atomicAdd(fs + 2, f2 * c4.z); atomicAdd(fs + 3, f3 * c4.w);
}

// ---------------- persistent level-loop kernel (internal nodes only) ----------------
#define TROWS 8

__global__ void __launch_bounds__(256, 2)
persist_kernel(const float* __restrict__ Wiouh, const float* __restrict__ Wfh,
               const float* __restrict__ Wh, const float* __restrict__ bh,
               const float* __restrict__ Wp, const float* __restrict__ bp,
               float* __restrict__ out) {
    __shared__ __align__(16) float As[TROWS][MDIM];   // h_sum rows, then reused as h rows
    __shared__ int gidS[TROWS], parS[TROWS], tokS[TROWS], ptokS[TROWS];
    const int t = threadIdx.x;
    const int maxlev = g_maxlev;

    for (int lev = maxlev; lev >= 0; lev--) {
        const int cntI = g_lvlcnt_int[lev];
        if (cntI == 0) continue;
        const int base = g_lvloff[lev];
        const int tiles = (cntI + TROWS - 1) / TROWS;

        for (int tile = blockIdx.x; tile < tiles; tile += gridDim.x) {
            int r0 = tile * TROWS;
            int nr = min(TROWS, cntI - r0);
            if (t < TROWS) {
                int g = (t < nr) ? g_order[base + r0 + t] : 0;
                gidS[t] = g;
                int p = g_parent[g];
                parS[t] = p;
                tokS[t] = g_tok[g];
                ptokS[t] = g_tok[p];
            }
            __syncthreads();
            #pragma unroll
            for (int r = 0; r < TROWS; r++)
                As[r][t] = (r < nr) ? g_hsum[(size_t)gidS[r] * MDIM + t] : 0.f;
            __syncthreads();

            // ===== GEMM1: iou = As(h_sum) @ Wiouh; thread t owns cols t, t+256, t+512
            float accI[TROWS], accO[TROWS], accU[TROWS];
            #pragma unroll
            for (int r = 0; r < TROWS; r++) { accI[r] = 0.f; accO[r] = 0.f; accU[r] = 0.f; }

            #pragma unroll 2
            for (int k4 = 0; k4 < MDIM / 4; k4++) {
                float4 a[TROWS];
                #pragma unroll
                for (int r = 0; r < TROWS; r++)
                    a[r] = *(const float4*)&As[r][k4 * 4];
                #pragma unroll
                for (int kk = 0; kk < 4; kk++) {
                    const float* wrow = &Wiouh[(size_t)(k4 * 4 + kk) * TM3];
                    float b0 = wrow[t], b1 = wrow[256 + t], b2 = wrow[512 + t];
                    #pragma unroll
                    for (int r = 0; r < TROWS; r++) {
                        float av = (kk == 0) ? a[r].x : (kk == 1) ? a[r].y : (kk == 2) ? a[r].z : a[r].w;
                        accI[r] += av * b0; accO[r] += av * b1; accU[r] += av * b2;
                    }
                }
            }

            // ===== cell update; h into As (reuse), c kept in regs
            __syncthreads();   // all GEMM1 reads of As done before overwrite
            float cr[TROWS], hr[TROWS];
            #pragma unroll
            for (int r = 0; r < TROWS; r++) {
                if (r < nr) {
                    int g = gidS[r];
                    const float* ea = &g_EA[(size_t)tokS[r] * TM3];
                    float ig = accI[r] + ea[t];
                    float og = accO[r] + ea[256 + t];
                    float ug = accU[r] + ea[512 + t];
                    float cc = sigm(ig) * tanhf(ug) + g_fcsum[(size_t)g * MDIM + t];
                    float hh = sigm(og) * tanhf(cc);
                    cr[r] = cc; hr[r] = hh;
                    As[r][t] = hh;
                    if (g == 0)            g_rootc[t] = cc;
                    else if (g == N_NODES) g_rootc[256 + t] = cc;
                } else { cr[r] = 0.f; hr[r] = 0.f; }
            }
            __syncthreads();

            // ===== GEMM2: fpre = As(h) @ Wfh; thread t owns col t
            float accF[TROWS];
            #pragma unroll
            for (int r = 0; r < TROWS; r++) accF[r] = 0.f;
            #pragma unroll 2
            for (int k4 = 0; k4 < MDIM / 4; k4++) {
                float4 a[TROWS];
                #pragma unroll
                for (int r = 0; r < TROWS; r++)
                    a[r] = *(const float4*)&As[r][k4 * 4];
                #pragma unroll
                for (int kk = 0; kk < 4; kk++) {
                    float w = Wfh[(size_t)(k4 * 4 + kk) * MDIM + t];
                    #pragma unroll
                    for (int r = 0; r < TROWS; r++) {
                        float av = (kk == 0) ? a[r].x : (kk == 1) ? a[r].y : (kk == 2) ? a[r].z : a[r].w;
                        accF[r] += av * w;
                    }
                }
            }

            // ===== scatter into parents
            #pragma unroll
            for (int r = 0; r < TROWS; r++) {
                if (r < nr) {
                    int g = gidS[r];
                    if (g != 0 && g != N_NODES) {
                        float f = sigm(accF[r] + g_EB[(size_t)ptokS[r] * MDIM + t]);
                        atomicAdd(&g_hsum[(size_t)parS[r] * MDIM + t], hr[r]);
                        atomicAdd(&g_fcsum[(size_t)parS[r] * MDIM + t], f * cr[r]);
                    }
                }
            }
            __syncthreads();
        }
        gsync();
    }

    // ===== similarity head (block 0)
    if (blockIdx.x == 0) {
        __shared__ float vec[512];
        __shared__ float hid[256];
        __shared__ float r0s[8], r1s[8];
        float cl = g_rootc[t], crt = g_rootc[256 + t];
        vec[t] = cl * crt;
        vec[256 + t] = fabsf(cl - crt);
        __syncthreads();
        float acc = bh[t];
        #pragma unroll 8
        for (int k = 0; k < 512; k++) acc += vec[k] * Wh[(size_t)k * 256 + t];
        hid[t] = 1.f / (1.f + expf(-acc));
        __syncthreads();
        float p0 = hid[t] * Wp[t * 2 + 0];
        float p1 = hid[t] * Wp[t * 2 + 1];
        #pragma unroll
        for (int o = 16; o > 0; o >>= 1) {
            p0 += __shfl_down_sync(0xffffffffu, p0, o);
            p1 += __shfl_down_sync(0xffffffffu, p1, o);
        }
        if ((t & 31) == 0) { r0s[t >> 5] = p0; r1s[t >> 5] = p1; }
        __syncthreads();
        if (t == 0) {
            float l0 = bp[0], l1 = bp[1];
            #pragma unroll
            for (int w = 0; w < 8; w++) { l0 += r0s[w]; l1 += r1s[w]; }
            float m = fmaxf(l0, l1);
            float e0 = expf(l0 - m), e1 = expf(l1 - m);
            float inv = 1.f / (e0 + e1);
            out[0] = e0 * inv;
            out[1] = e1 * inv;
        }
    }
}

// ---------------- host launch ----------------
extern "C" void kernel_launch(void* const* d_in, const int* in_sizes, int n_in,
                              void* d_out, int out_size) {
    const int*   l_tokens = (const int*)  d_in[0];
    const int*   l_parent = (const int*)  d_in[1];
    const int*   r_tokens = (const int*)  d_in[2];
    const int*   r_parent = (const int*)  d_in[3];
    const float* emb_W    = (const float*)d_in[4];
    const float* Wioux    = (const float*)d_in[5];
    const float* bioux    = (const float*)d_in[6];
    const float* Wiouh    = (const float*)d_in[7];
    const float* biouh    = (const float*)d_in[8];
    const float* Wfx      = (const float*)d_in[9];
    const float* bfx      = (const float*)d_in[10];
    const float* Wfh      = (const float*)d_in[11];
    const float* bfh      = (const float*)d_in[12];
    const float* Wh       = (const float*)d_in[13];
    const float* bh       = (const float*)d_in[14];
    const float* Wp       = (const float*)d_in[15];
    const float* bp       = (const float*)d_in[16];
    float* out = (float*)d_out;

    clear_kernel<<<32768, 256>>>();
    setup_kernel<<<NN / 256, 256>>>(l_tokens, l_parent, r_tokens, r_parent);
    for (int it = 0; it < 8; it++)
        doubling_kernel<<<NN / 256, 256>>>(it & 1);
    hist_kernel<<<NN / 256, 256>>>();
    scan_kernel<<<1, 32>>>();
    scatter_kernel<<<NN / 256, 256>>>();
    eaeb_kernel<<<dim3(VOCABSZ, 4), 256>>>(emb_W, Wioux, bioux, biouh, Wfx, bfx, bfh);
    leafhc_kernel<<<VOCABSZ, 256>>>();
    leaffh_kernel<<<VOCABSZ, 256>>>(Wfh);
    leafscatter_kernel<<<NN * 64 / 256, 256>>>();

    persist_kernel<<<NB, 256>>>(Wiouh, Wfh, Wh, bh, Wp, bp, out);
}

// round 6
// speedup vs baseline: 2.4787x; 1.2327x over previous
#include <cuda_runtime.h>
#include <cuda_bf16.h>
#include <math.h>

#define N_NODES 65536
#define NN      131072          // both trees
#define MDIM    256
#define TM3     768
#define VOCABSZ 1000
#define MAXLEV  64
#define NB      296             // persistent grid: 2 CTAs/SM on 148 SMs

#define AS_STRIDE 260           // 260%32=4 -> conflict-free A frags
#define BS_STRIDE 776           // 776%32=8 -> conflict-free B frags

// ---------------- device scratch (static, allowed) ----------------
__device__ float g_hsum[(size_t)NN * MDIM];
__device__ float g_fcsum[(size_t)NN * MDIM];
__device__ float g_EA[(size_t)VOCABSZ * TM3];
__device__ float g_EB[(size_t)VOCABSZ * MDIM];
__device__ float g_HL[(size_t)VOCABSZ * MDIM];
__device__ float g_CL[(size_t)VOCABSZ * MDIM];
__device__ float g_FH[(size_t)VOCABSZ * MDIM];
__device__ float g_rootc[2 * MDIM];

__device__ int g_parent[NN];
__device__ int g_tok[NN];
__device__ int g_anc[2][NN];
__device__ int g_dist[2][NN];
__device__ int g_childcnt[NN];
__device__ int g_lvlcnt_int[MAXLEV];
__device__ int g_lvlcnt_leaf[MAXLEV];
__device__ int g_lvloff[MAXLEV];
__device__ int g_curs_int[MAXLEV];
__device__ int g_curs_leaf[MAXLEV];
__device__ int g_order[NN];
__device__ int g_maxlev;

__device__ unsigned g_bcount = 0;
__device__ volatile unsigned g_bgen = 0;

__device__ __forceinline__ float sigm(float x) { return 1.f / (1.f + __expf(-x)); }

__device__ __forceinline__ unsigned tf32u(float x) {
    unsigned y;
    asm("cvt.rna.tf32.f32 %0, %1;" : "=r"(y) : "f"(x));
    return y;
}

__device__ __forceinline__ void mma8(float4& d, unsigned a0, unsigned a1, unsigned a2, unsigned a3,
                                     unsigned b0, unsigned b1) {
    asm volatile("mma.sync.aligned.m16n8k8.row.col.f32.tf32.tf32.f32 "
        "{%0,%1,%2,%3},{%4,%5,%6,%7},{%8,%9},{%0,%1,%2,%3};"
        : "+f"(d.x), "+f"(d.y), "+f"(d.z), "+f"(d.w)
        : "r"(a0), "r"(a1), "r"(a2), "r"(a3), "r"(b0), "r"(b1));
}

__device__ __forceinline__ void gsync() {
    __syncthreads();
    if (threadIdx.x == 0) {
        __threadfence();
        unsigned my = g_bgen;
        if (atomicInc(&g_bcount, gridDim.x - 1) == gridDim.x - 1) {
            g_bgen = my + 1;
        } else {
            while (g_bgen == my) { }
        }
        __threadfence();
    }
    __syncthreads();
}

// ---------------- setup ----------------
__global__ void clear_kernel() {
    size_t i = (size_t)blockIdx.x * blockDim.x + threadIdx.x;
    size_t tot4 = (size_t)NN * MDIM / 4;
    if (i < tot4) {
        float4 z = make_float4(0.f, 0.f, 0.f, 0.f);
        reinterpret_cast<float4*>(g_hsum)[i] = z;
        reinterpret_cast<float4*>(g_fcsum)[i] = z;
    }
    if (i < NN) g_childcnt[i] = 0;
    if (i < MAXLEV) {
        g_lvlcnt_int[i] = 0; g_lvlcnt_leaf[i] = 0;
        g_curs_int[i] = 0;   g_curs_leaf[i] = 0;
    }
}

__global__ void setup_kernel(const int* __restrict__ lt, const int* __restrict__ lp,
                             const int* __restrict__ rt, const int* __restrict__ rp) {
    int g = blockIdx.x * blockDim.x + threadIdx.x;
    if (g >= NN) return;
    int tok, par; bool root;
    if (g < N_NODES) {
        tok = lt[g]; root = (g == 0);
        par = root ? g : lp[g];
    } else {
        int i = g - N_NODES;
        tok = rt[i]; root = (i == 0);
        par = root ? g : (N_NODES + rp[i]);
    }
    g_tok[g] = tok; g_parent[g] = par;
    g_anc[0][g] = par;
    g_dist[0][g] = root ? 0 : 1;
    if (!root) atomicAdd(&g_childcnt[par], 1);
}

__global__ void doubling_kernel(int src) {
    int g = blockIdx.x * blockDim.x + threadIdx.x;
    if (g >= NN) return;
    int a = g_anc[src][g];
    g_dist[1 - src][g] = g_dist[src][g] + g_dist[src][a];
    g_anc[1 - src][g]  = g_anc[src][a];
}

__global__ void hist_kernel() {
    int g = blockIdx.x * blockDim.x + threadIdx.x;
    if (g >= NN) return;
    int d = g_dist[0][g]; if (d > MAXLEV - 1) d = MAXLEV - 1;
    if (g_childcnt[g] > 0) atomicAdd(&g_lvlcnt_int[d], 1);
    else                   atomicAdd(&g_lvlcnt_leaf[d], 1);
}

__global__ void scan_kernel() {
    if (threadIdx.x == 0) {
        int off = 0, maxl = 0;
        for (int l = 0; l < MAXLEV; l++) {
            g_lvloff[l] = off;
            int c = g_lvlcnt_int[l] + g_lvlcnt_leaf[l];
            if (c > 0) maxl = l;
            off += c;
        }
        g_maxlev = maxl;
    }
}

__global__ void scatter_kernel() {
    int g = blockIdx.x * blockDim.x + threadIdx.x;
    if (g >= NN) return;
    int d = g_dist[0][g]; if (d > MAXLEV - 1) d = MAXLEV - 1;
    int base = g_lvloff[d];
    if (g_childcnt[g] > 0) {
        int p = atomicAdd(&g_curs_int[d], 1);
        g_order[base + p] = g;
    } else {
        int p = atomicAdd(&g_curs_leaf[d], 1);
        g_order[base + g_lvlcnt_int[d] + p] = g;
    }
}

__global__ void eaeb_kernel(const float* __restrict__ emb,
                            const float* __restrict__ Wioux, const float* __restrict__ bioux,
                            const float* __restrict__ biouh,
                            const float* __restrict__ Wfx, const float* __restrict__ bfx,
                            const float* __restrict__ bfh) {
    int v = blockIdx.x;
    int chunk = blockIdx.y;
    __shared__ float xs[MDIM];
    int t = threadIdx.x;
    xs[t] = emb[(size_t)v * MDIM + t];
    __syncthreads();
    if (chunk < 3) {
        int j = chunk * 256 + t;
        float acc = bioux[j] + biouh[j];
        #pragma unroll 8
        for (int k = 0; k < MDIM; k++) acc += xs[k] * Wioux[(size_t)k * TM3 + j];
        g_EA[(size_t)v * TM3 + j] = acc;
    } else {
        int j = t;
        float acc = bfx[j] + bfh[j];
        #pragma unroll 8
        for (int k = 0; k < MDIM; k++) acc += xs[k] * Wfx[(size_t)k * MDIM + j];
        g_EB[(size_t)v * MDIM + j] = acc;
    }
}

__global__ void leafhc_kernel() {
    int v = blockIdx.x, t = threadIdx.x;
    const float* ea = &g_EA[(size_t)v * TM3];
    float cc = sigm(ea[t]) * tanhf(ea[512 + t]);
    float hh = sigm(ea[256 + t]) * tanhf(cc);
    g_CL[(size_t)v * MDIM + t] = cc;
    g_HL[(size_t)v * MDIM + t] = hh;
}

__global__ void leaffh_kernel(const float* __restrict__ Wfh) {
    int v = blockIdx.x, t = threadIdx.x;
    __shared__ float hs[MDIM];
    hs[t] = g_HL[(size_t)v * MDIM + t];
    __syncthreads();
    float acc = 0.f;
    #pragma unroll 8
    for (int k = 0; k < MDIM; k++) acc += hs[k] * Wfh[(size_t)k * MDIM + t];
    g_FH[(size_t)v * MDIM + t] = acc;
}

__global__ void leafscatter_kernel() {
    int idx = blockIdx.x * blockDim.x + threadIdx.x;
    int g = idx >> 6;
    int c = (idx & 63) * 4;
    if (g >= NN) return;
    if (g_childcnt[g] > 0) return;
    int p = g_parent[g];
    int tok = g_tok[g], ptok = g_tok[p];
    float4 h4 = *(const float4*)&g_HL[(size_t)tok * MDIM + c];
    float4 c4 = *(const float4*)&g_CL[(size_t)tok * MDIM + c];
    float4 fh = *(const float4*)&g_FH[(size_t)tok * MDIM + c];
    float4 eb = *(const float4*)&g_EB[(size_t)ptok * MDIM + c];
    float f0 = sigm(fh.x + eb.x), f1 = sigm(fh.y + eb.y);
    float f2 = sigm(fh.z + eb.z), f3 = sigm(fh.w + eb.w);
    float* hs = &g_hsum[(size_t)p * MDIM + c];
    float* fs = &g_fcsum[(size_t)p * MDIM + c];
    atomicAdd(hs + 0, h4.x); atomicAdd(hs + 1, h4.y);
    atomicAdd(hs + 2, h4.z); atomicAdd(hs + 3, h4.w);
    atomicAdd(fs + 0, f0 * c4.x); atomicAdd(fs + 1, f1 * c4.y);
    atomicAdd(fs + 2, f2 * c4.z); atomicAdd(fs + 3, f3 * c4.w);
}

// ---------------- persistent tensor-core level-loop kernel ----------------
__global__ void __launch_bounds__(256, 2)
persist_kernel(const float* __restrict__ Wiouh, const float* __restrict__ Wfh,
               const float* __restrict__ Wh, const float* __restrict__ bh,
               const float* __restrict__ Wp, const float* __restrict__ bp,
               float* __restrict__ out) {
    __shared__ unsigned AsU[16 * AS_STRIDE];   // h_sum (tf32), then h (tf32)
    __shared__ unsigned BsU[8 * BS_STRIDE];    // staged weight k-chunk (tf32)
    __shared__ int gidS[16], parS[16], tokS[16], ptokS[16];

    const int t   = threadIdx.x;
    const int w   = t >> 5;
    const int lane = t & 31;
    const int gi  = lane >> 2;     // groupID 0..7
    const int tig = lane & 3;      // thread-in-group 0..3
    const int maxlev = g_maxlev;

    for (int lev = maxlev; lev >= 0; lev--) {
        const int cntI = g_lvlcnt_int[lev];
        if (cntI == 0) continue;
        const int base = g_lvloff[lev];
        const int tiles = (cntI + 15) >> 4;

        for (int tile = blockIdx.x; tile < tiles; tile += gridDim.x) {
            int r0 = tile * 16;
            int nr = min(16, cntI - r0);
            if (t < 16) {
                int g = (t < nr) ? g_order[base + r0 + t] : 0;
                gidS[t] = g;
                int p = g_parent[g];
                parS[t] = p;
                tokS[t] = g_tok[g];
                ptokS[t] = g_tok[p];
            }
            __syncthreads();
            // stage A = h_sum rows (tf32-rounded); 1024 float4 / 256 threads
            #pragma unroll
            for (int i = 0; i < 4; i++) {
                int fi = t + i * 256;            // float4 index
                int r = fi >> 6, c4 = fi & 63;
                float4 v = (r < nr) ? *(const float4*)&g_hsum[(size_t)gidS[r] * MDIM + c4 * 4]
                                    : make_float4(0.f, 0.f, 0.f, 0.f);
                uint4 u = make_uint4(tf32u(v.x), tf32u(v.y), tf32u(v.z), tf32u(v.w));
                *(uint4*)&AsU[r * AS_STRIDE + c4 * 4] = u;
            }

            // ===== GEMM1: iou[16x768] = A @ Wiouh, mma tf32 =====
            float4 accI[4], accO[4], accU[4];
            #pragma unroll
            for (int b = 0; b < 4; b++) {
                accI[b] = make_float4(0.f, 0.f, 0.f, 0.f);
                accO[b] = make_float4(0.f, 0.f, 0.f, 0.f);
                accU[b] = make_float4(0.f, 0.f, 0.f, 0.f);
            }
            for (int kc = 0; kc < 32; kc++) {
                __syncthreads();
                #pragma unroll
                for (int i = 0; i < 6; i++) {
                    int fi = t + i * 256;        // 0..1535 float4s
                    int r = fi / 192, c4 = fi - r * 192;
                    float4 v = *(const float4*)&Wiouh[(size_t)(kc * 8 + r) * TM3 + c4 * 4];
                    uint4 u = make_uint4(tf32u(v.x), tf32u(v.y), tf32u(v.z), tf32u(v.w));
                    *(uint4*)&BsU[r * BS_STRIDE + c4 * 4] = u;
                }
                __syncthreads();
                int k0 = kc * 8;
                unsigned a0 = AsU[gi * AS_STRIDE + k0 + tig];
                unsigned a1 = AsU[(gi + 8) * AS_STRIDE + k0 + tig];
                unsigned a2 = AsU[gi * AS_STRIDE + k0 + tig + 4];
                unsigned a3 = AsU[(gi + 8) * AS_STRIDE + k0 + tig + 4];
                #pragma unroll
                for (int b = 0; b < 4; b++) {
                    int cb = 8 * w + 64 * b;
                    unsigned b0 = BsU[tig * BS_STRIDE + cb + gi];
                    unsigned b1 = BsU[(tig + 4) * BS_STRIDE + cb + gi];
                    mma8(accI[b], a0, a1, a2, a3, b0, b1);
                    b0 = BsU[tig * BS_STRIDE + cb + 256 + gi];
                    b1 = BsU[(tig + 4) * BS_STRIDE + cb + 256 + gi];
                    mma8(accO[b], a0, a1, a2, a3, b0, b1);
                    b0 = BsU[tig * BS_STRIDE + cb + 512 + gi];
                    b1 = BsU[(tig + 4) * BS_STRIDE + cb + 512 + gi];
                    mma8(accU[b], a0, a1, a2, a3, b0, b1);
                }
            }
            __syncthreads();   // all A reads done before overwriting As with h

            // ===== cell update (in registers; h->As tf32, c/h kept fp32) =====
            float ccr[16], hhr[16];
            #pragma unroll
            for (int b = 0; b < 4; b++) {
                int c0 = 8 * w + 64 * b + 2 * tig;
                #pragma unroll
                for (int rr = 0; rr < 2; rr++) {
                    int r = gi + rr * 8;
                    int g = gidS[r];
                    int tok = tokS[r];
                    float vI0 = rr ? accI[b].z : accI[b].x;
                    float vI1 = rr ? accI[b].w : accI[b].y;
                    float vO0 = rr ? accO[b].z : accO[b].x;
                    float vO1 = rr ? accO[b].w : accO[b].y;
                    float vU0 = rr ? accU[b].z : accU[b].x;
                    float vU1 = rr ? accU[b].w : accU[b].y;
                    const float* ea = g_EA + (size_t)tok * TM3 + c0;
                    float2 eI = *(const float2*)ea;
                    float2 eO = *(const float2*)(ea + 256);
                    float2 eU = *(const float2*)(ea + 512);
                    float2 fc = *(const float2*)(g_fcsum + (size_t)g * MDIM + c0);
                    float cc0 = sigm(vI0 + eI.x) * tanhf(vU0 + eU.x) + fc.x;
                    float cc1 = sigm(vI1 + eI.y) * tanhf(vU1 + eU.y) + fc.y;
                    float hh0 = sigm(vO0 + eO.x) * tanhf(cc0);
                    float hh1 = sigm(vO1 + eO.y) * tanhf(cc1);
                    AsU[r * AS_STRIDE + c0]     = tf32u(hh0);
                    AsU[r * AS_STRIDE + c0 + 1] = tf32u(hh1);
                    int ix = b * 4 + rr * 2;
                    ccr[ix] = cc0; ccr[ix + 1] = cc1;
                    hhr[ix] = hh0; hhr[ix + 1] = hh1;
                    if (r < nr) {
                        if (g == 0) {
                            g_rootc[c0] = cc0; g_rootc[c0 + 1] = cc1;
                        } else if (g == N_NODES) {
                            g_rootc[MDIM + c0] = cc0; g_rootc[MDIM + c0 + 1] = cc1;
                        }
                    }
                }
            }

            // ===== GEMM2: fpre[16x256] = h @ Wfh + scatter =====
            if (lev > 0) {
                float4 acc2[4];
                #pragma unroll
                for (int b = 0; b < 4; b++) acc2[b] = make_float4(0.f, 0.f, 0.f, 0.f);
                for (int kc = 0; kc < 32; kc++) {
                    __syncthreads();
                    #pragma unroll
                    for (int i = 0; i < 2; i++) {
                        int fi = t + i * 256;    // 0..511 float4s
                        int r = fi >> 6, c4 = fi & 63;
                        float4 v = *(const float4*)&Wfh[(size_t)(kc * 8 + r) * MDIM + c4 * 4];
                        uint4 u = make_uint4(tf32u(v.x), tf32u(v.y), tf32u(v.z), tf32u(v.w));
                        *(uint4*)&BsU[r * BS_STRIDE + c4 * 4] = u;
                    }
                    __syncthreads();
                    int k0 = kc * 8;
                    unsigned a0 = AsU[gi * AS_STRIDE + k0 + tig];
                    unsigned a1 = AsU[(gi + 8) * AS_STRIDE + k0 + tig];
                    unsigned a2 = AsU[gi * AS_STRIDE + k0 + tig + 4];
                    unsigned a3 = AsU[(gi + 8) * AS_STRIDE + k0 + tig + 4];
                    #pragma unroll
                    for (int b = 0; b < 4; b++) {
                        int cb = 8 * w + 64 * b;
                        unsigned b0 = BsU[tig * BS_STRIDE + cb + gi];
                        unsigned b1 = BsU[(tig + 4) * BS_STRIDE + cb + gi];
                        mma8(acc2[b], a0, a1, a2, a3, b0, b1);
                    }
                }
                #pragma unroll
                for (int b = 0; b < 4; b++) {
                    int c0 = 8 * w + 64 * b + 2 * tig;
                    #pragma unroll
                    for (int rr = 0; rr < 2; rr++) {
                        int r = gi + rr * 8;
                        if (r < nr) {
                            int g = gidS[r];
                            if (g != 0 && g != N_NODES) {
                                int p = parS[r];
                                float2 eb = *(const float2*)(g_EB + (size_t)ptokS[r] * MDIM + c0);
                                float F0 = rr ? acc2[b].z : acc2[b].x;
                                float F1 = rr ? acc2[b].w : acc2[b].y;
                                float f0 = sigm(F0 + eb.x);
                                float f1 = sigm(F1 + eb.y);
                                int ix = b * 4 + rr * 2;
                                float* hs = g_hsum + (size_t)p * MDIM + c0;
                                float* fs = g_fcsum + (size_t)p * MDIM + c0;
                                atomicAdd(hs,     hhr[ix]);
                                atomicAdd(hs + 1, hhr[ix + 1]);
                                atomicAdd(fs,     f0 * ccr[ix]);
                                atomicAdd(fs + 1, f1 * ccr[ix + 1]);
                            }
                        }
                    }
                }
            }
            __syncthreads();   // protect As/gid restage next tile
        }
        gsync();
    }

    // ===== similarity head (block 0) =====
    if (blockIdx.x == 0) {
        float* vec = (float*)AsU;          // 512
        float* hid = vec + 512;            // 256
        float* red = hid + 256;            // 16
        float cl = g_rootc[t], crt = g_rootc[256 + t];
        vec[t] = cl * crt;
        vec[256 + t] = fabsf(cl - crt);
        __syncthreads();
        float acc = bh[t];
        #pragma unroll 8
        for (int k = 0; k < 512; k++) acc += vec[k] * Wh[(size_t)k * 256 + t];
        hid[t] = 1.f / (1.f + expf(-acc));
        __syncthreads();
        float p0 = hid[t] * Wp[t * 2 + 0];
        float p1 = hid[t] * Wp[t * 2 + 1];
        #pragma unroll
        for (int o = 16; o > 0; o >>= 1) {
            p0 += __shfl_down_sync(0xffffffffu, p0, o);
            p1 += __shfl_down_sync(0xffffffffu, p1, o);
        }
        if ((t & 31) == 0) { red[t >> 5] = p0; red[8 + (t >> 5)] = p1; }
        __syncthreads();
        if (t == 0) {
            float l0 = bp[0], l1 = bp[1];
            #pragma unroll
            for (int q = 0; q < 8; q++) { l0 += red[q]; l1 += red[8 + q]; }
            float m = fmaxf(l0, l1);
            float e0 = expf(l0 - m), e1 = expf(l1 - m);
            float inv = 1.f / (e0 + e1);
            out[0] = e0 * inv;
            out[1] = e1 * inv;
        }
    }
}

// ---------------- host launch ----------------
extern "C" void kernel_launch(void* const* d_in, const int* in_sizes, int n_in,
                              void* d_out, int out_size) {
    const int*   l_tokens = (const int*)  d_in[0];
    const int*   l_parent = (const int*)  d_in[1];
    const int*   r_tokens = (const int*)  d_in[2];
    const int*   r_parent = (const int*)  d_in[3];
    const float* emb_W    = (const float*)d_in[4];
    const float* Wioux    = (const float*)d_in[5];
    const float* bioux    = (const float*)d_in[6];
    const float* Wiouh    = (const float*)d_in[7];
    const float* biouh    = (const float*)d_in[8];
    const float* Wfx      = (const float*)d_in[9];
    const float* bfx      = (const float*)d_in[10];
    const float* Wfh      = (const float*)d_in[11];
    const float* bfh      = (const float*)d_in[12];
    const float* Wh       = (const float*)d_in[13];
    const float* bh       = (const float*)d_in[14];
    const float* Wp       = (const float*)d_in[15];
    const float* bp       = (const float*)d_in[16];
    float* out = (float*)d_out;

    clear_kernel<<<32768, 256>>>();
    setup_kernel<<<NN / 256, 256>>>(l_tokens, l_parent, r_tokens, r_parent);
    for (int it = 0; it < 8; it++)
        doubling_kernel<<<NN / 256, 256>>>(it & 1);
    hist_kernel<<<NN / 256, 256>>>();
    scan_kernel<<<1, 32>>>();
    scatter_kernel<<<NN / 256, 256>>>();
    eaeb_kernel<<<dim3(VOCABSZ, 4), 256>>>(emb_W, Wioux, bioux, biouh, Wfx, bfx, bfh);
    leafhc_kernel<<<VOCABSZ, 256>>>();
    leaffh_kernel<<<VOCABSZ, 256>>>(Wfh);
    leafscatter_kernel<<<NN * 64 / 256, 256>>>();

    persist_kernel<<<NB, 256>>>(Wiouh, Wfh, Wh, bh, Wp, bp, out);
}

// round 7
// speedup vs baseline: 4.3072x; 1.7377x over previous
#include <cuda_runtime.h>
#include <cuda_bf16.h>
#include <math.h>

#define N_NODES 65536
#define NN      131072          // both trees
#define MDIM    256
#define TM3     768
#define VOCABSZ 1000
#define MAXLEV  64
#define NB      296             // persistent grid: 2 CTAs/SM on 148 SMs

#define AS_STRIDE 260           // 260%32=4 -> conflict-free A frags

// ---------------- device scratch (static, allowed) ----------------
__device__ float g_hsum[(size_t)NN * MDIM];
__device__ float g_fcsum[(size_t)NN * MDIM];
__device__ float g_EA[(size_t)VOCABSZ * TM3];
__device__ float g_EB[(size_t)VOCABSZ * MDIM];
__device__ float g_HL[(size_t)VOCABSZ * MDIM];
__device__ float g_CL[(size_t)VOCABSZ * MDIM];
__device__ float g_FH[(size_t)VOCABSZ * MDIM];
__device__ float g_rootc[2 * MDIM];

// fragment-packed tf32 weights: [kc][colblock][lane] -> (b0,b1)
__device__ uint2 g_Wp1[32 * 96 * 32];   // Wiouh, 768 cols = 96 colblocks
__device__ uint2 g_Wp2[32 * 32 * 32];   // Wfh,   256 cols = 32 colblocks

__device__ int g_parent[NN];
__device__ int g_tok[NN];
__device__ int g_anc[2][NN];
__device__ int g_dist[2][NN];
__device__ int g_childcnt[NN];
__device__ int g_lvlcnt_int[MAXLEV];
__device__ int g_lvlcnt_leaf[MAXLEV];
__device__ int g_lvloff[MAXLEV];
__device__ int g_curs_int[MAXLEV];
__device__ int g_curs_leaf[MAXLEV];
__device__ int g_order[NN];
__device__ int g_maxlev;

__device__ unsigned g_bcount = 0;
__device__ volatile unsigned g_bgen = 0;

__device__ __forceinline__ float sigm(float x) { return 1.f / (1.f + __expf(-x)); }

__device__ __forceinline__ unsigned tf32u(float x) {
    unsigned y;
    asm("cvt.rna.tf32.f32 %0, %1;" : "=r"(y) : "f"(x));
    return y;
}

__device__ __forceinline__ void mma8(float4& d, unsigned a0, unsigned a1, unsigned a2, unsigned a3,
                                     unsigned b0, unsigned b1) {
    asm volatile("mma.sync.aligned.m16n8k8.row.col.f32.tf32.tf32.f32 "
        "{%0,%1,%2,%3},{%4,%5,%6,%7},{%8,%9},{%0,%1,%2,%3};"
        : "+f"(d.x), "+f"(d.y), "+f"(d.z), "+f"(d.w)
        : "r"(a0), "r"(a1), "r"(a2), "r"(a3), "r"(b0), "r"(b1));
}

__device__ __forceinline__ void red2(float* p, float a, float b) {
    asm volatile("red.global.add.v2.f32 [%0], {%1, %2};"
                 :: "l"(p), "f"(a), "f"(b) : "memory");
}
__device__ __forceinline__ void red4(float* p, float a, float b, float c, float d) {
    asm volatile("red.global.add.v4.f32 [%0], {%1, %2, %3, %4};"
                 :: "l"(p), "f"(a), "f"(b), "f"(c), "f"(d) : "memory");
}

__device__ __forceinline__ void gsync() {
    __syncthreads();
    if (threadIdx.x == 0) {
        __threadfence();
        unsigned my = g_bgen;
        if (atomicInc(&g_bcount, gridDim.x - 1) == gridDim.x - 1) {
            g_bgen = my + 1;
        } else {
            while (g_bgen == my) { }
        }
        __threadfence();
    }
    __syncthreads();
}

// ---------------- setup ----------------
__global__ void clear_kernel() {
    size_t i = (size_t)blockIdx.x * blockDim.x + threadIdx.x;
    size_t tot4 = (size_t)NN * MDIM / 4;
    if (i < tot4) {
        float4 z = make_float4(0.f, 0.f, 0.f, 0.f);
        reinterpret_cast<float4*>(g_hsum)[i] = z;
        reinterpret_cast<float4*>(g_fcsum)[i] = z;
    }
    if (i < NN) g_childcnt[i] = 0;
    if (i < MAXLEV) {
        g_lvlcnt_int[i] = 0; g_lvlcnt_leaf[i] = 0;
        g_curs_int[i] = 0;   g_curs_leaf[i] = 0;
    }
}

__global__ void setup_kernel(const int* __restrict__ lt, const int* __restrict__ lp,
                             const int* __restrict__ rt, const int* __restrict__ rp) {
    int g = blockIdx.x * blockDim.x + threadIdx.x;
    if (g >= NN) return;
    int tok, par; bool root;
    if (g < N_NODES) {
        tok = lt[g]; root = (g == 0);
        par = root ? g : lp[g];
    } else {
        int i = g - N_NODES;
        tok = rt[i]; root = (i == 0);
        par = root ? g : (N_NODES + rp[i]);
    }
    g_tok[g] = tok; g_parent[g] = par;
    g_anc[0][g] = par;
    g_dist[0][g] = root ? 0 : 1;
    if (!root) atomicAdd(&g_childcnt[par], 1);
}

__global__ void doubling_kernel(int src) {
    int g = blockIdx.x * blockDim.x + threadIdx.x;
    if (g >= NN) return;
    int a = g_anc[src][g];
    g_dist[1 - src][g] = g_dist[src][g] + g_dist[src][a];
    g_anc[1 - src][g]  = g_anc[src][a];
}

__global__ void hist_kernel() {
    int g = blockIdx.x * blockDim.x + threadIdx.x;
    if (g >= NN) return;
    int d = g_dist[0][g]; if (d > MAXLEV - 1) d = MAXLEV - 1;
    if (g_childcnt[g] > 0) atomicAdd(&g_lvlcnt_int[d], 1);
    else                   atomicAdd(&g_lvlcnt_leaf[d], 1);
}

__global__ void scan_kernel() {
    if (threadIdx.x == 0) {
        int off = 0, maxl = 0;
        for (int l = 0; l < MAXLEV; l++) {
            g_lvloff[l] = off;
            int c = g_lvlcnt_int[l] + g_lvlcnt_leaf[l];
            if (c > 0) maxl = l;
            off += c;
        }
        g_maxlev = maxl;
    }
}

__global__ void scatter_kernel() {
    int g = blockIdx.x * blockDim.x + threadIdx.x;
    if (g >= NN) return;
    int d = g_dist[0][g]; if (d > MAXLEV - 1) d = MAXLEV - 1;
    int base = g_lvloff[d];
    if (g_childcnt[g] > 0) {
        int p = atomicAdd(&g_curs_int[d], 1);
        g_order[base + p] = g;
    } else {
        int p = atomicAdd(&g_curs_leaf[d], 1);
        g_order[base + g_lvlcnt_int[d] + p] = g;
    }
}

// weight pack kernels: lane holds (b0,b1) = W[k0+tig][col], W[k0+tig+4][col]
__global__ void pack1_kernel(const float* __restrict__ W) {   // Wiouh 256x768
    int idx = blockIdx.x * blockDim.x + threadIdx.x;
    if (idx >= 32 * 96 * 32) return;
    int lane = idx & 31;
    int cbi = (idx >> 5) % 96;
    int kc = idx / (96 * 32);
    int tig = lane & 3, gi = lane >> 2;
    int col = cbi * 8 + gi;
    float v0 = W[(size_t)(kc * 8 + tig) * TM3 + col];
    float v1 = W[(size_t)(kc * 8 + tig + 4) * TM3 + col];
    g_Wp1[idx] = make_uint2(tf32u(v0), tf32u(v1));
}
__global__ void pack2_kernel(const float* __restrict__ W) {   // Wfh 256x256
    int idx = blockIdx.x * blockDim.x + threadIdx.x;
    if (idx >= 32 * 32 * 32) return;
    int lane = idx & 31;
    int cbi = (idx >> 5) % 32;
    int kc = idx / (32 * 32);
    int tig = lane & 3, gi = lane >> 2;
    int col = cbi * 8 + gi;
    float v0 = W[(size_t)(kc * 8 + tig) * MDIM + col];
    float v1 = W[(size_t)(kc * 8 + tig + 4) * MDIM + col];
    g_Wp2[idx] = make_uint2(tf32u(v0), tf32u(v1));
}

// EA/EB: tiled over 8 vocab rows per block (weight reuse x8)
__global__ void eaeb_kernel(const float* __restrict__ emb,
                            const float* __restrict__ Wioux, const float* __restrict__ bioux,
                            const float* __restrict__ biouh,
                            const float* __restrict__ Wfx, const float* __restrict__ bfx,
                            const float* __restrict__ bfh) {
    int v0 = blockIdx.x * 8;
    int chunk = blockIdx.y;
    __shared__ float xs[8][MDIM];
    int t = threadIdx.x;
    #pragma unroll
    for (int i = 0; i < 8; i++) {
        int idx = t + i * 256;
        xs[idx >> 8][idx & 255] = emb[(size_t)v0 * MDIM + idx];
    }
    __syncthreads();
    float acc[8];
    #pragma unroll
    for (int r = 0; r < 8; r++) acc[r] = 0.f;
    if (chunk < 3) {
        int j = chunk * 256 + t;
        for (int k = 0; k < MDIM; k++) {
            float w = Wioux[(size_t)k * TM3 + j];
            #pragma unroll
            for (int r = 0; r < 8; r++) acc[r] += xs[r][k] * w;
        }
        float bias = bioux[j] + biouh[j];
        #pragma unroll
        for (int r = 0; r < 8; r++)
            g_EA[(size_t)(v0 + r) * TM3 + j] = acc[r] + bias;
    } else {
        int j = t;
        for (int k = 0; k < MDIM; k++) {
            float w = Wfx[(size_t)k * MDIM + j];
            #pragma unroll
            for (int r = 0; r < 8; r++) acc[r] += xs[r][k] * w;
        }
        float bias = bfx[j] + bfh[j];
        #pragma unroll
        for (int r = 0; r < 8; r++)
            g_EB[(size_t)(v0 + r) * MDIM + j] = acc[r] + bias;
    }
}

__global__ void leafhc_kernel() {
    int v = blockIdx.x, t = threadIdx.x;
    const float* ea = &g_EA[(size_t)v * TM3];
    float cc = sigm(ea[t]) * tanhf(ea[512 + t]);
    float hh = sigm(ea[256 + t]) * tanhf(cc);
    g_CL[(size_t)v * MDIM + t] = cc;
    g_HL[(size_t)v * MDIM + t] = hh;
}

// FH = HL @ Wfh, tiled over 8 vocab rows
__global__ void leaffh_kernel(const float* __restrict__ Wfh) {
    int v0 = blockIdx.x * 8;
    int t = threadIdx.x;
    __shared__ float hs[8][MDIM];
    #pragma unroll
    for (int i = 0; i < 8; i++) {
        int idx = t + i * 256;
        hs[idx >> 8][idx & 255] = g_HL[(size_t)v0 * MDIM + idx];
    }
    __syncthreads();
    float acc[8];
    #pragma unroll
    for (int r = 0; r < 8; r++) acc[r] = 0.f;
    for (int k = 0; k < MDIM; k++) {
        float w = Wfh[(size_t)k * MDIM + t];
        #pragma unroll
        for (int r = 0; r < 8; r++) acc[r] += hs[r][k] * w;
    }
    #pragma unroll
    for (int r = 0; r < 8; r++)
        g_FH[(size_t)(v0 + r) * MDIM + t] = acc[r];
}

__global__ void leafscatter_kernel() {
    int idx = blockIdx.x * blockDim.x + threadIdx.x;
    int g = idx >> 6;
    int c = (idx & 63) * 4;
    if (g >= NN) return;
    if (g_childcnt[g] > 0) return;
    int p = g_parent[g];
    int tok = g_tok[g], ptok = g_tok[p];
    float4 h4 = *(const float4*)&g_HL[(size_t)tok * MDIM + c];
    float4 c4 = *(const float4*)&g_CL[(size_t)tok * MDIM + c];
    float4 fh = *(const float4*)&g_FH[(size_t)tok * MDIM + c];
    float4 eb = *(const float4*)&g_EB[(size_t)ptok * MDIM + c];
    float f0 = sigm(fh.x + eb.x), f1 = sigm(fh.y + eb.y);
    float f2 = sigm(fh.z + eb.z), f3 = sigm(fh.w + eb.w);
    red4(&g_hsum[(size_t)p * MDIM + c], h4.x, h4.y, h4.z, h4.w);
    red4(&g_fcsum[(size_t)p * MDIM + c], f0 * c4.x, f1 * c4.y, f2 * c4.z, f3 * c4.w);
}

// ---------------- persistent tensor-core level-loop kernel ----------------
__global__ void __launch_bounds__(256, 2)
persist_kernel(const float* __restrict__ Wh, const float* __restrict__ bh,
               const float* __restrict__ Wp, const float* __restrict__ bp,
               float* __restrict__ out) {
    __shared__ unsigned AsU[16 * AS_STRIDE];   // h_sum (tf32), then h (tf32)
    __shared__ int gidS[16], parS[16], tokS[16], ptokS[16];

    const int t    = threadIdx.x;
    const int w    = t >> 5;
    const int lane = t & 31;
    const int gi   = lane >> 2;
    const int tig  = lane & 3;
    const int maxlev = g_maxlev;

    for (int lev = maxlev; lev >= 0; lev--) {
        const int cntI = g_lvlcnt_int[lev];
        if (cntI == 0) continue;
        const int base = g_lvloff[lev];
        const int tiles = (cntI + 15) >> 4;

        for (int tile = blockIdx.x; tile < tiles; tile += gridDim.x) {
            int r0 = tile * 16;
            int nr = min(16, cntI - r0);
            if (t < 16) {
                int g = (t < nr) ? g_order[base + r0 + t] : 0;
                gidS[t] = g;
                int p = g_parent[g];
                parS[t] = p;
                tokS[t] = g_tok[g];
                ptokS[t] = g_tok[p];
            }
            __syncthreads();
            // stage A = h_sum rows (tf32)
            #pragma unroll
            for (int i = 0; i < 4; i++) {
                int fi = t + i * 256;
                int r = fi >> 6, c4 = fi & 63;
                float4 v = (r < nr) ? *(const float4*)&g_hsum[(size_t)gidS[r] * MDIM + c4 * 4]
                                    : make_float4(0.f, 0.f, 0.f, 0.f);
                uint4 u = make_uint4(tf32u(v.x), tf32u(v.y), tf32u(v.z), tf32u(v.w));
                *(uint4*)&AsU[r * AS_STRIDE + c4 * 4] = u;
            }
            __syncthreads();

            // ===== GEMM1: iou[16x768] = A @ Wiouh (B direct from packed global) =====
            float4 accI[4], accO[4], accU[4];
            #pragma unroll
            for (int b = 0; b < 4; b++) {
                accI[b] = make_float4(0.f, 0.f, 0.f, 0.f);
                accO[b] = make_float4(0.f, 0.f, 0.f, 0.f);
                accU[b] = make_float4(0.f, 0.f, 0.f, 0.f);
            }
            #pragma unroll 2
            for (int kc = 0; kc < 32; kc++) {
                int k0 = kc * 8;
                unsigned a0 = AsU[gi * AS_STRIDE + k0 + tig];
                unsigned a1 = AsU[(gi + 8) * AS_STRIDE + k0 + tig];
                unsigned a2 = AsU[gi * AS_STRIDE + k0 + tig + 4];
                unsigned a3 = AsU[(gi + 8) * AS_STRIDE + k0 + tig + 4];
                const uint2* wp = g_Wp1 + (size_t)kc * 96 * 32 + lane;
                #pragma unroll
                for (int b = 0; b < 4; b++) {
                    int cbi = w + 8 * b;
                    uint2 bI = wp[(size_t)cbi * 32];
                    uint2 bO = wp[(size_t)(cbi + 32) * 32];
                    uint2 bU = wp[(size_t)(cbi + 64) * 32];
                    mma8(accI[b], a0, a1, a2, a3, bI.x, bI.y);
                    mma8(accO[b], a0, a1, a2, a3, bO.x, bO.y);
                    mma8(accU[b], a0, a1, a2, a3, bU.x, bU.y);
                }
            }
            __syncthreads();   // all A reads done before overwriting As with h

            // ===== cell update (h -> As tf32, c kept fp32 in regs) =====
            float ccr[16];
            #pragma unroll
            for (int b = 0; b < 4; b++) {
                int c0 = 8 * w + 64 * b + 2 * tig;
                #pragma unroll
                for (int rr = 0; rr < 2; rr++) {
                    int r = gi + rr * 8;
                    int g = gidS[r];
                    int tok = tokS[r];
                    float vI0 = rr ? accI[b].z : accI[b].x;
                    float vI1 = rr ? accI[b].w : accI[b].y;
                    float vO0 = rr ? accO[b].z : accO[b].x;
                    float vO1 = rr ? accO[b].w : accO[b].y;
                    float vU0 = rr ? accU[b].z : accU[b].x;
                    float vU1 = rr ? accU[b].w : accU[b].y;
                    const float* ea = g_EA + (size_t)tok * TM3 + c0;
                    float2 eI = *(const float2*)ea;
                    float2 eO = *(const float2*)(ea + 256);
                    float2 eU = *(const float2*)(ea + 512);
                    float2 fc = *(const float2*)(g_fcsum + (size_t)g * MDIM + c0);
                    float cc0 = sigm(vI0 + eI.x) * tanhf(vU0 + eU.x) + fc.x;
                    float cc1 = sigm(vI1 + eI.y) * tanhf(vU1 + eU.y) + fc.y;
                    float hh0 = sigm(vO0 + eO.x) * tanhf(cc0);
                    float hh1 = sigm(vO1 + eO.y) * tanhf(cc1);
                    AsU[r * AS_STRIDE + c0]     = tf32u(hh0);
                    AsU[r * AS_STRIDE + c0 + 1] = tf32u(hh1);
                    int ix = b * 4 + rr * 2;
                    ccr[ix] = cc0; ccr[ix + 1] = cc1;
                    if (r < nr) {
                        if (g == 0) {
                            g_rootc[c0] = cc0; g_rootc[c0 + 1] = cc1;
                        } else if (g == N_NODES) {
                            g_rootc[MDIM + c0] = cc0; g_rootc[MDIM + c0 + 1] = cc1;
                        }
                    }
                }
            }
            __syncthreads();

            // ===== GEMM2: fpre[16x256] = h @ Wfh + parent scatter =====
            if (lev > 0) {
                float4 acc2[4];
                #pragma unroll
                for (int b = 0; b < 4; b++) acc2[b] = make_float4(0.f, 0.f, 0.f, 0.f);
                #pragma unroll 2
                for (int kc = 0; kc < 32; kc++) {
                    int k0 = kc * 8;
                    unsigned a0 = AsU[gi * AS_STRIDE + k0 + tig];
                    unsigned a1 = AsU[(gi + 8) * AS_STRIDE + k0 + tig];
                    unsigned a2 = AsU[gi * AS_STRIDE + k0 + tig + 4];
                    unsigned a3 = AsU[(gi + 8) * AS_STRIDE + k0 + tig + 4];
                    const uint2* wp = g_Wp2 + (size_t)kc * 32 * 32 + lane;
                    #pragma unroll
                    for (int b = 0; b < 4; b++) {
                        uint2 bb = wp[(size_t)(w + 8 * b) * 32];
                        mma8(acc2[b], a0, a1, a2, a3, bb.x, bb.y);
                    }
                }
                #pragma unroll
                for (int b = 0; b < 4; b++) {
                    int c0 = 8 * w + 64 * b + 2 * tig;
                    #pragma unroll
                    for (int rr = 0; rr < 2; rr++) {
                        int r = gi + rr * 8;
                        if (r < nr) {
                            int g = gidS[r];
                            if (g != 0 && g != N_NODES) {
                                int p = parS[r];
                                float2 eb = *(const float2*)(g_EB + (size_t)ptokS[r] * MDIM + c0);
                                float F0 = rr ? acc2[b].z : acc2[b].x;
                                float F1 = rr ? acc2[b].w : acc2[b].y;
                                float f0 = sigm(F0 + eb.x);
                                float f1 = sigm(F1 + eb.y);
                                float hh0 = __uint_as_float(AsU[r * AS_STRIDE + c0]);
                                float hh1 = __uint_as_float(AsU[r * AS_STRIDE + c0 + 1]);
                                int ix = b * 4 + rr * 2;
                                red2(g_hsum + (size_t)p * MDIM + c0, hh0, hh1);
                                red2(g_fcsum + (size_t)p * MDIM + c0, f0 * ccr[ix], f1 * ccr[ix + 1]);
                            }
                        }
                    }
                }
            }
            __syncthreads();
        }
        gsync();
    }

    // ===== similarity head (block 0) =====
    if (blockIdx.x == 0) {
        float* vec = (float*)AsU;          // 512
        float* hid = vec + 512;            // 256
        float* red = hid + 256;            // 16
        float cl = g_rootc[t], crt = g_rootc[256 + t];
        vec[t] = cl * crt;
        vec[256 + t] = fabsf(cl - crt);
        __syncthreads();
        float acc = bh[t];
        #pragma unroll 8
        for (int k = 0; k < 512; k++) acc += vec[k] * Wh[(size_t)k * 256 + t];
        hid[t] = 1.f / (1.f + expf(-acc));
        __syncthreads();
        float p0 = hid[t] * Wp[t * 2 + 0];
        float p1 = hid[t] * Wp[t * 2 + 1];
        #pragma unroll
        for (int o = 16; o > 0; o >>= 1) {
            p0 += __shfl_down_sync(0xffffffffu, p0, o);
            p1 += __shfl_down_sync(0xffffffffu, p1, o);
        }
        if ((t & 31) == 0) { red[t >> 5] = p0; red[8 + (t >> 5)] = p1; }
        __syncthreads();
        if (t == 0) {
            float l0 = bp[0], l1 = bp[1];
            #pragma unroll
            for (int q = 0; q < 8; q++) { l0 += red[q]; l1 += red[8 + q]; }
            float m = fmaxf(l0, l1);
            float e0 = expf(l0 - m), e1 = expf(l1 - m);
            float inv = 1.f / (e0 + e1);
            out[0] = e0 * inv;
            out[1] = e1 * inv;
        }
    }
}

// ---------------- host launch ----------------
extern "C" void kernel_launch(void* const* d_in, const int* in_sizes, int n_in,
                              void* d_out, int out_size) {
    const int*   l_tokens = (const int*)  d_in[0];
    const int*   l_parent = (const int*)  d_in[1];
    const int*   r_tokens = (const int*)  d_in[2];
    const int*   r_parent = (const int*)  d_in[3];
    const float* emb_W    = (const float*)d_in[4];
    const float* Wioux    = (const float*)d_in[5];
    const float* bioux    = (const float*)d_in[6];
    const float* Wiouh    = (const float*)d_in[7];
    const float* biouh    = (const float*)d_in[8];
    const float* Wfx      = (const float*)d_in[9];
    const float* bfx      = (const float*)d_in[10];
    const float* Wfh      = (const float*)d_in[11];
    const float* bfh      = (const float*)d_in[12];
    const float* Wh       = (const float*)d_in[13];
    const float* bh       = (const float*)d_in[14];
    const float* Wp       = (const float*)d_in[15];
    const float* bp       = (const float*)d_in[16];
    float* out = (float*)d_out;

    clear_kernel<<<32768, 256>>>();
    setup_kernel<<<NN / 256, 256>>>(l_tokens, l_parent, r_tokens, r_parent);
    for (int it = 0; it < 6; it++)
        doubling_kernel<<<NN / 256, 256>>>(it & 1);
    hist_kernel<<<NN / 256, 256>>>();
    scan_kernel<<<1, 32>>>();
    scatter_kernel<<<NN / 256, 256>>>();
    pack1_kernel<<<(32 * 96 * 32 + 255) / 256, 256>>>(Wiouh);
    pack2_kernel<<<(32 * 32 * 32 + 255) / 256, 256>>>(Wfh);
    eaeb_kernel<<<dim3(VOCABSZ / 8, 4), 256>>>(emb_W, Wioux, bioux, biouh, Wfx, bfx, bfh);
    leafhc_kernel<<<VOCABSZ, 256>>>();
    leaffh_kernel<<<VOCABSZ / 8, 256>>>(Wfh);
    leafscatter_kernel<<<NN * 64 / 256, 256>>>();

    persist_kernel<<<NB, 256>>>(Wh, bh, Wp, bp, out);
}